// round 14
// baseline (speedup 1.0000x reference)
#include <cuda_runtime.h>
#include <math.h>
#include <stdint.h>

#define NN   4096
#define KK   32
#define DD   64
#define BSZ  8
#define TT   32
#define HSZ  256
#define ROWS (BSZ*NN)

typedef unsigned long long u64;

// ================= persistent device scratch =================
__device__ float4 g_wsig4[ROWS*KK/4];
__device__ float  g_d[ROWS];
__device__ float  g_dec[ROWS];
__device__ float  g_prim[ROWS*DD];
__device__ float  g_sconst[(size_t)ROWS*HSZ];   // [row][256]
__device__ float  g_mconst[(size_t)ROWS*HSZ];
__device__ float2 g_h2[ROWS*DD/2];              // [row][32 float2]
__device__ float2 g_msg2[2][ROWS*DD/2];
__device__ float  g_WsC[129*HSZ];               // const-GEMM weights [j][h]
__device__ float  g_WmC[129*HSZ];
// fragment-packed bf16 weights: phase p*4096 .. : uint4 = {b0h,b1h,b0l,b1l}
// p0 = Wsi (wide 64x256), p1 = Ws2 (narrow 256x64), p2 = Wmh, p3 = Wm2
__device__ uint4  g_Wpk[4*4096];

// ================= helpers =================
__device__ __forceinline__ float ftanh(float x) {
    float ax = fabsf(x);
    float e  = __expf(-2.f*ax);
    float t  = __fdividef(1.f - e, 1.f + e);
    return copysignf(t, x);
}
__device__ __forceinline__ float fsigmoid(float x) {
    return __fdividef(1.f, 1.f + __expf(-x));
}
__device__ __forceinline__ u64 pack2(float x) {
    u64 r; unsigned xi = __float_as_uint(x);
    asm("mov.b64 %0, {%1,%1};" : "=l"(r) : "r"(xi));
    return r;
}
__device__ __forceinline__ float2 unpack2(u64 v) {
    unsigned lo, hi;
    asm("mov.b64 {%0,%1}, %2;" : "=r"(lo), "=r"(hi) : "l"(v));
    return make_float2(__uint_as_float(lo), __uint_as_float(hi));
}
__device__ __forceinline__ void ffma2(u64& d, u64 a, u64 b) {
    asm("fma.rn.f32x2 %0, %1, %2, %0;" : "+l"(d) : "l"(a), "l"(b));
}
// split (a,b) into bf16 hi-pair and lo-pair; lower 16 bits = a
__device__ __forceinline__ void split2(float a, float b, uint32_t& hi, uint32_t& lo) {
    uint32_t h;
    asm("cvt.rn.bf16x2.f32 %0, %1, %2;" : "=r"(h) : "f"(b), "f"(a));
    float ra = a - __uint_as_float(h << 16);
    float rb = b - __uint_as_float(h & 0xffff0000u);
    uint32_t l;
    asm("cvt.rn.bf16x2.f32 %0, %1, %2;" : "=r"(l) : "f"(rb), "f"(ra));
    hi = h; lo = l;
}
__device__ __forceinline__ void ldm_x4(uint32_t* r, uint32_t addr) {
    asm volatile("ldmatrix.sync.aligned.m8n8.x4.shared.b16 {%0,%1,%2,%3}, [%4];"
        : "=r"(r[0]), "=r"(r[1]), "=r"(r[2]), "=r"(r[3]) : "r"(addr));
}
__device__ __forceinline__ void mma_bf16(float* d, const uint32_t* a,
                                         uint32_t b0, uint32_t b1) {
    asm volatile("mma.sync.aligned.m16n8k16.row.col.f32.bf16.bf16.f32 "
        "{%0,%1,%2,%3}, {%4,%5,%6,%7}, {%8,%9}, {%0,%1,%2,%3};"
        : "+f"(d[0]), "+f"(d[1]), "+f"(d[2]), "+f"(d[3])
        : "r"(a[0]), "r"(a[1]), "r"(a[2]), "r"(a[3]), "r"(b0), "r"(b1));
}
__device__ __forceinline__ uint32_t smem_u32(const void* p) {
    uint32_t a;
    asm("{ .reg .u64 t; cvta.to.shared.u64 t, %1; cvt.u32.u64 %0, t; }"
        : "=r"(a) : "l"(p));
    return a;
}

// ================= init: copy state, build const-W, pack mma weights =================
__global__ void k_init(const float* __restrict__ h_in, const float* __restrict__ msg_in,
                       const float* __restrict__ sw1, const float* __restrict__ sw2,
                       const float* __restrict__ mw1, const float* __restrict__ mw2)
{
    int i0 = blockIdx.x*blockDim.x + threadIdx.x;
    int stride = gridDim.x*blockDim.x;
    float* gh  = (float*)g_h2;
    float* gm0 = (float*)g_msg2[0];
    for (int i = i0; i < ROWS*DD; i += stride) { gh[i] = h_in[i]; gm0[i] = msg_in[i]; }
    for (int i = i0; i < 129*HSZ; i += stride) {
        int j = i >> 8, h = i & 255;
        g_WsC[i] = (j < 128) ? sw1[h*193 + 64 + j] : sw1[h*193 + 192];
        g_WmC[i] = (j < 128) ? mw1[h*192 + 64 + j] : 0.f;
    }
    for (int e = i0; e < 4*4096; e += stride) {
        int p = e >> 12, r = e & 4095;
        int lane = r & 31, q = r >> 5;
        int NT = (p == 0 || p == 2) ? 32 : 8;
        int kt = q / NT, nt = q - kt*NT;
        int k0 = kt*16 + (lane & 3)*2;
        int n  = nt*8 + (lane >> 2);
        float w00, w01, w10, w11;
        if (p == 0)      { const float* s = sw1 + (size_t)n*193;
                           w00 = s[k0]; w01 = s[k0+1]; w10 = s[k0+8]; w11 = s[k0+9]; }
        else if (p == 1) { const float* s = sw2 + (size_t)n*256;
                           w00 = s[k0]; w01 = s[k0+1]; w10 = s[k0+8]; w11 = s[k0+9]; }
        else if (p == 2) { const float* s = mw1 + (size_t)n*192;
                           w00 = s[k0]; w01 = s[k0+1]; w10 = s[k0+8]; w11 = s[k0+9]; }
        else             { const float* s = mw2 + (size_t)n*256;
                           w00 = s[k0]; w01 = s[k0+1]; w10 = s[k0+8]; w11 = s[k0+9]; }
        uint32_t b0h, b0l, b1h, b1l;
        split2(w00, w01, b0h, b0l);
        split2(w10, w11, b1h, b1l);
        g_Wpk[e] = make_uint4(b0h, b1h, b0l, b1l);
    }
}

// ================= per-neuron modulation MLP (unchanged) =================
__global__ void k_mod(const float* __restrict__ h_in, const float* __restrict__ heb,
                      const float* __restrict__ dec_in, const float* __restrict__ prim_in,
                      const float* __restrict__ wconn_in,
                      const float* __restrict__ mw1, const float* __restrict__ mb1,
                      const float* __restrict__ mw2, const float* __restrict__ mb2,
                      const float* __restrict__ nid)
{
    const int n = blockIdx.x;
    const int tid = threadIdx.x;
    const int warp = tid >> 5, lane = tid & 31;
    __shared__ float xs[BSZ*225];
    __shared__ float hid[BSZ*64];
    __shared__ float dlt[BSZ*97];

    for (int i = tid; i < BSZ*225; i += 256) {
        int b = i / 225, j = i - b*225;
        size_t bn = (size_t)b*NN + n;
        float v;
        if (j < 32)        v = heb[bn*32 + j];
        else if (j < 96)   v = h_in[bn*64 + (j-32)];
        else if (j == 96)  v = dec_in[bn];
        else if (j < 161)  v = prim_in[bn*64 + (j-97)];
        else               v = nid[(size_t)n*64 + (j-161)];
        xs[i] = v;
    }
    __syncthreads();

    const float* w1 = mw1 + (size_t)n*64*225;
    for (int hh = warp; hh < 64; hh += 8) {
        float acc[BSZ];
        #pragma unroll
        for (int b = 0; b < BSZ; b++) acc[b] = 0.f;
        for (int j = lane; j < 225; j += 32) {
            float w = w1[hh*225 + j];
            #pragma unroll
            for (int b = 0; b < BSZ; b++) acc[b] += w * xs[b*225 + j];
        }
        #pragma unroll
        for (int off = 16; off; off >>= 1) {
            #pragma unroll
            for (int b = 0; b < BSZ; b++) acc[b] += __shfl_xor_sync(0xffffffffu, acc[b], off);
        }
        if (lane == 0) {
            float bb = mb1[(size_t)n*64 + hh];
            #pragma unroll
            for (int b = 0; b < BSZ; b++) hid[b*64 + hh] = ftanh(acc[b] + bb);
        }
    }
    __syncthreads();

    const float* w2 = mw2 + (size_t)n*64*97;
    for (int o = warp; o < 97; o += 8) {
        float acc[BSZ];
        #pragma unroll
        for (int b = 0; b < BSZ; b++) acc[b] = 0.f;
        #pragma unroll
        for (int j2 = 0; j2 < 2; ++j2) {
            int j = lane + 32*j2;
            float w = w2[(size_t)j*97 + o];
            #pragma unroll
            for (int b = 0; b < BSZ; b++) acc[b] += w * hid[b*64 + j];
        }
        #pragma unroll
        for (int off = 16; off; off >>= 1) {
            #pragma unroll
            for (int b = 0; b < BSZ; b++) acc[b] += __shfl_xor_sync(0xffffffffu, acc[b], off);
        }
        if (lane == 0) {
            float bb = mb2[(size_t)n*97 + o];
            #pragma unroll
            for (int b = 0; b < BSZ; b++) dlt[b*97 + o] = acc[b] + bb;
        }
    }
    __syncthreads();

    float* wsig = (float*)g_wsig4;
    for (int i = tid; i < BSZ*KK; i += 256) {
        int b = i >> 5, k = i & 31;
        size_t bn = (size_t)b*NN + n;
        wsig[bn*32 + k] = fsigmoid(wconn_in[bn*32 + k] + dlt[b*97 + k]);
    }
    if (tid < BSZ) {
        size_t bn = (size_t)tid*NN + n;
        float v = dec_in[bn] + dlt[tid*97 + 32];
        g_dec[bn] = v;
        g_d[bn] = fsigmoid(v);
    }
    if (warp < BSZ) {
        int b = warp;
        size_t bn = (size_t)b*NN + n;
        float p0 = prim_in[bn*64 + lane]      + dlt[b*97 + 33 + lane];
        float p1 = prim_in[bn*64 + lane + 32] + dlt[b*97 + 33 + lane + 32];
        float ss = p0*p0 + p1*p1;
        #pragma unroll
        for (int off = 16; off; off >>= 1) ss += __shfl_xor_sync(0xffffffffu, ss, off);
        float sc = rsqrtf(ss*(1.f/64.f) + 1e-6f);
        g_prim[bn*64 + lane]      = p0*sc;
        g_prim[bn*64 + lane + 32] = p1*sc;
    }
}

// ================= state_const / msg_const (unchanged) =================
__global__ __launch_bounds__(256, 4)
void k_const(const float* __restrict__ sb1, const float* __restrict__ mb1_,
             const float* __restrict__ nid)
{
    __shared__ float xs[64*132];
    const int tid = threadIdx.x;
    const int r0 = blockIdx.x * 64;
    const int which = blockIdx.y;
    const float* WC = which ? g_WsC : g_WmC;
    const float* b1 = which ? sb1 : mb1_;
    float* outp     = which ? g_sconst : g_mconst;

    for (int i = tid; i < 64*132; i += 256) {
        int rr = i / 132, j = i - rr*132;
        size_t r = (size_t)(r0 + rr);
        int nn_ = (int)(r & (NN-1));
        float v = 0.f;
        if (j < 64)        v = g_prim[r*64 + j];
        else if (j < 128)  v = nid[(size_t)nn_*64 + (j-64)];
        else if (j == 128) v = g_dec[r];
        xs[i] = v;
    }
    __syncthreads();

    const int ty = tid >> 5, tx = tid & 31;
    float acc[8][8];
    #pragma unroll
    for (int i = 0; i < 8; i++)
        #pragma unroll
        for (int u = 0; u < 8; u++) acc[i][u] = 0.f;
    for (int j = 0; j < 129; ++j) {
        float a[8], w[8];
        #pragma unroll
        for (int i = 0; i < 8; i++) a[i] = xs[(ty*8+i)*132 + j];
        #pragma unroll
        for (int u = 0; u < 8; u++) w[u] = __ldg(WC + j*256 + tx + 32*u);
        #pragma unroll
        for (int i = 0; i < 8; i++)
            #pragma unroll
            for (int u = 0; u < 8; u++) acc[i][u] += a[i]*w[u];
    }
    #pragma unroll
    for (int i = 0; i < 8; i++) {
        int r = r0 + ty*8 + i;
        #pragma unroll
        for (int u = 0; u < 8; u++) {
            int c = tx + 32*u;
            outp[(size_t)r*256 + c] = acc[i][u] + __ldg(b1 + c);
        }
    }
}

// ================= pipelined fused wide->tanh->narrow (registers only) =================
// All pointers pre-offset by lane; offsets below are compile-time so each LDG
// stream uses ONE address register (minimizes spill pressure at the 128-reg cap).
// WW = Wwide + ln + kt*64 ; pA/pB = cst rows + q*2 + kt*16 ; WN = Wnarrow + ln + kt*256
__device__ __forceinline__ void wide_mma_p(
    const uint32_t A0[4][4], const uint32_t A1[4][4],
    const uint4* __restrict__ WW, const float* __restrict__ pA,
    const float* __restrict__ pB, float d[2][2][4], float2 cc_[2][2])
{
    #pragma unroll
    for (int half = 0; half < 2; ++half) {
        #pragma unroll
        for (int s = 0; s < 2; ++s)
            #pragma unroll
            for (int i = 0; i < 4; ++i) d[half][s][i] = 0.f;
        #pragma unroll
        for (int wk = 0; wk < 4; ++wk) {
            uint4 u = __ldg(WW + wk*1024 + half*32);
            mma_bf16(d[half][0], A0[wk], u.x, u.y);   // chain depth 4
            mma_bf16(d[half][1], A0[wk], u.z, u.w);   // chain depth 8
            mma_bf16(d[half][1], A1[wk], u.x, u.y);
        }
        cc_[half][0] = *(const float2*)(pA + half*8);
        cc_[half][1] = *(const float2*)(pB + half*8);
    }
}

__device__ __forceinline__ void wide_epi(const float d[2][2][4], const float2 cc_[2][2],
                                         uint32_t ah[4], uint32_t al[4])
{
    #pragma unroll
    for (int half = 0; half < 2; ++half) {
        float h0 = ftanh(d[half][0][0] + d[half][1][0] + cc_[half][0].x);
        float h1 = ftanh(d[half][0][1] + d[half][1][1] + cc_[half][0].y);
        float h2 = ftanh(d[half][0][2] + d[half][1][2] + cc_[half][1].x);
        float h3 = ftanh(d[half][0][3] + d[half][1][3] + cc_[half][1].y);
        split2(h0, h1, ah[half*2],   al[half*2]);
        split2(h2, h3, ah[half*2+1], al[half*2+1]);
    }
}

__device__ __forceinline__ void narrow_step_p(const uint32_t ah[4], const uint32_t al[4],
                                              const uint4* __restrict__ WN,
                                              float nacc[8][4])
{
    #pragma unroll
    for (int nt = 0; nt < 8; ++nt) {
        uint4 u = __ldg(WN + nt*32);
        mma_bf16(nacc[nt], ah, u.x, u.y);
        mma_bf16(nacc[nt], ah, u.z, u.w);
        mma_bf16(nacc[nt], al, u.x, u.y);
    }
}

__device__ __forceinline__ void fused_wide_narrow(
    const uint32_t Ah[4][4], const uint32_t Al[4][4],
    const uint4* __restrict__ Wwide_ln, const uint4* __restrict__ Wnarrow_ln,
    const float* __restrict__ cstA, const float* __restrict__ cstB,
    float nacc[8][4])
{
    #pragma unroll
    for (int nt = 0; nt < 8; nt++)
        #pragma unroll
        for (int i = 0; i < 4; i++) nacc[nt][i] = 0.f;

    float d[2][2][4]; float2 cc_[2][2];
    uint32_t ah[4], al[4];
    const uint4* WW = Wwide_ln;
    const float* pA = cstA;
    const float* pB = cstB;
    const uint4* WN = Wnarrow_ln;

    wide_mma_p(Ah, Al, WW, pA, pB, d, cc_);
    wide_epi(d, cc_, ah, al);
    #pragma unroll 1
    for (int kt = 1; kt < 16; ++kt) {
        WW += 64; pA += 16; pB += 16;
        float d2[2][2][4]; float2 cc2[2][2];
        wide_mma_p(Ah, Al, WW, pA, pB, d2, cc2);   // fills pipe
        narrow_step_p(ah, al, WN, nacc);           // overlaps wide latency
        WN += 256;
        wide_epi(d2, cc2, ah, al);
    }
    narrow_step_p(ah, al, WN, nacc);
}

// ================= fused step: gather -> (wide+narrow)x2, register-chained =================
#define A_STRIDE   144
#define AH_OFF     0
#define AL_OFF     2304
#define WARP_BYTES 4608
#define STEP_SMEM  (4*WARP_BYTES)

__global__ __launch_bounds__(128, 4)
void k_step(int t, const float* __restrict__ cc, const int* __restrict__ conn,
            const float* __restrict__ nid, const float* __restrict__ sb2,
            const float* __restrict__ mb2, float* __restrict__ out)
{
    extern __shared__ char smem[];
    const int tid = threadIdx.x;
    const int w   = tid >> 5, ln = tid & 31;
    char*    wmem = smem + w*WARP_BYTES;
    const uint32_t wsm = smem_u32(smem) + w*WARP_BYTES;

    const int b      = blockIdx.y;
    const int ntblk  = blockIdx.x;
    const int n0     = ntblk*64;
    const int nfirst = n0 + w*16;
    const int sel    = t & 1;
    const size_t growbase = (size_t)b*NN + nfirst;

    // ---- phase 0: gather (+inject) -> bf16 h/l A-tile in smem ----
    {
        const u64*    mq  = (const u64*)g_msg2[sel] + (size_t)b*NN*32;
        const int4*   cn4 = (const int4*)conn;
        const float4* ws4 = (const float4*)g_wsig4;
        #pragma unroll 1
        for (int g = 0; g < 16; ++g) {
            const int n = nfirst + g;
            const size_t cb = (size_t)n*8;
            const size_t wb = ((size_t)b*NN + n)*8;
            u64 a0 = 0ull, a1 = 0ull;
            #pragma unroll
            for (int kq = 0; kq < 8; ++kq) {
                int4   id = __ldg(cn4 + cb + kq);
                float4 wt = __ldg(ws4 + wb + kq);
                ffma2(a0, pack2(wt.x), mq[(size_t)id.x*32 + ln]);
                ffma2(a1, pack2(wt.y), mq[(size_t)id.y*32 + ln]);
                ffma2(a0, pack2(wt.z), mq[(size_t)id.z*32 + ln]);
                ffma2(a1, pack2(wt.w), mq[(size_t)id.w*32 + ln]);
            }
            float2 v0 = unpack2(a0), v1 = unpack2(a1);
            float x0 = v0.x + v1.x, x1 = v0.y + v1.y;
            if ((n & 127) < 4) {
                float2 cv = *(const float2*)(cc + ((size_t)b*TT + t)*2048 + (n>>7)*64 + ln*2);
                x0 += cv.x; x1 += cv.y;
            }
            uint32_t hi, lo;
            split2(x0, x1, hi, lo);
            *(uint32_t*)(wmem + AH_OFF + g*A_STRIDE + ln*4) = hi;
            *(uint32_t*)(wmem + AL_OFF + g*A_STRIDE + ln*4) = lo;
        }
    }
    __syncwarp();

    // load gather A-frags once; smem A region free afterwards.
    // These SAME registers are reused for the phase-3 A-fragments (h).
    uint32_t Ah[4][4], Al[4][4];
    {
        const int row = ln & 15;
        const uint32_t coff = (uint32_t)((ln >> 4) << 4);
        #pragma unroll
        for (int kt = 0; kt < 4; kt++) {
            uint32_t ad = wsm + AH_OFF + row*A_STRIDE + kt*32 + coff;
            ldm_x4(Ah[kt], ad);
            ldm_x4(Al[kt], ad + (AL_OFF - AH_OFF));
        }
    }
    __syncwarp();

    const int gr = ln >> 2, q = ln & 3;
    float nacc[8][4];

    // ---- phases 1+2: hid = tanh(recv@Wsi + sconst); nacc = hid@Ws2 ----
    fused_wide_narrow(Ah, Al, g_Wpk + ln, g_Wpk + 4096 + ln,
                      g_sconst + (growbase + gr)*256 + q*2,
                      g_sconst + (growbase + gr + 8)*256 + q*2, nacc);

    // ---- phase 2 epilogue: h update; OVERWRITE Ah/Al with phase-3 A-frags ----
    {
        const float dv0 = g_d[growbase + gr];
        const float dv1 = g_d[growbase + gr + 8];
        float2* hb0 = g_h2 + (growbase + gr)*32 + q;       // + nt*4 (compile-time)
        float2* hb1 = g_h2 + (growbase + gr + 8)*32 + q;
        const float2* sbq = (const float2*)(sb2 + q*2);    // + nt*4 in float2 units
        #pragma unroll
        for (int nt = 0; nt < 8; ++nt) {
            float2 bb = sbq[nt*4];
            // row gr
            {
                float2 ho = hb0[nt*4];
                float u0 = ftanh(nacc[nt][0] + bb.x), u1 = ftanh(nacc[nt][1] + bb.y);
                float hv0 = dv0*ho.x + (1.f-dv0)*u0, hv1 = dv0*ho.y + (1.f-dv0)*u1;
                hb0[nt*4] = make_float2(hv0, hv1);
                split2(hv0, hv1, Ah[nt>>1][(nt&1)*2], Al[nt>>1][(nt&1)*2]);
            }
            // row gr+8
            {
                float2 ho = hb1[nt*4];
                float u0 = ftanh(nacc[nt][2] + bb.x), u1 = ftanh(nacc[nt][3] + bb.y);
                float hv0 = dv1*ho.x + (1.f-dv1)*u0, hv1 = dv1*ho.y + (1.f-dv1)*u1;
                hb1[nt*4] = make_float2(hv0, hv1);
                split2(hv0, hv1, Ah[nt>>1][(nt&1)*2+1], Al[nt>>1][(nt&1)*2+1]);
            }
        }
    }

    // ---- phases 3+4: mh = tanh(h@Wmh + mconst); nacc = mh@Wm2 ----
    fused_wide_narrow(Ah, Al, g_Wpk + 2*4096 + ln, g_Wpk + 3*4096 + ln,
                      g_mconst + (growbase + gr)*256 + q*2,
                      g_mconst + (growbase + gr + 8)*256 + q*2, nacc);

    // ---- phase 4 epilogue: msg = tanh(.+mb2)+nid; readout ----
    {
        const int roflag = (ntblk & 1) && (w == 3);
        float2* mo0 = g_msg2[sel ^ 1] + (growbase + gr)*32 + q;
        float2* mo1 = g_msg2[sel ^ 1] + (growbase + gr + 8)*32 + q;
        const float2* nv0 = (const float2*)(nid + (size_t)(nfirst + gr)*64) + q;
        const float2* nv1 = (const float2*)(nid + (size_t)(nfirst + gr + 8)*64) + q;
        const float2* mbq = (const float2*)(mb2 + q*2);
        float* s_ro = (float*)wmem;      // gather A region, free now
        #pragma unroll
        for (int nt = 0; nt < 8; ++nt) {
            float2 bb = mbq[nt*4];
            // row gr
            {
                float2 nv = nv0[nt*4];
                float m0 = ftanh(nacc[nt][0] + bb.x) + nv.x;
                float m1 = ftanh(nacc[nt][1] + bb.y) + nv.y;
                mo0[nt*4] = make_float2(m0, m1);
            }
            // row gr+8
            {
                float2 nv = nv1[nt*4];
                float m0 = ftanh(nacc[nt][2] + bb.x) + nv.x;
                float m1 = ftanh(nacc[nt][3] + bb.y) + nv.y;
                mo1[nt*4] = make_float2(m0, m1);
                if (roflag && gr >= 4)
                    *(float2*)(s_ro + (gr-4)*64 + nt*8 + q*2) = make_float2(m0, m1);
            }
        }
        __syncwarp();
        if (roflag) {
            size_t obase = ((size_t)b*TT + t)*2048 + (ntblk >> 1)*64;
            float v0 = 0.25f*(s_ro[ln]      + s_ro[64+ln]  + s_ro[128+ln] + s_ro[192+ln]);
            float v1 = 0.25f*(s_ro[32+ln]   + s_ro[96+ln]  + s_ro[160+ln] + s_ro[224+ln]);
            out[obase + ln]      = v0;
            out[obase + 32 + ln] = v1;
        }
    }
}

// ================= launcher =================
extern "C" void kernel_launch(void* const* d_in, const int* in_sizes, int n_in,
                              void* d_out, int out_size)
{
    const float* cc      = (const float*)d_in[0];
    const float* h_in    = (const float*)d_in[1];
    const float* msg_in  = (const float*)d_in[2];
    const float* wconn   = (const float*)d_in[3];
    const float* declog  = (const float*)d_in[4];
    const float* prim_in = (const float*)d_in[5];
    const float* heb     = (const float*)d_in[6];
    const float* sw1     = (const float*)d_in[7];
    const float* sb1     = (const float*)d_in[8];
    const float* sw2     = (const float*)d_in[9];
    const float* sb2     = (const float*)d_in[10];
    const float* mw1     = (const float*)d_in[11];
    const float* mb1     = (const float*)d_in[12];
    const float* mw2     = (const float*)d_in[13];
    const float* mb2     = (const float*)d_in[14];
    const float* modw1   = (const float*)d_in[15];
    const float* modb1   = (const float*)d_in[16];
    const float* modw2   = (const float*)d_in[17];
    const float* modb2   = (const float*)d_in[18];
    const float* nid     = (const float*)d_in[19];
    const int*   conn    = (const int*)d_in[20];
    float* out = (float*)d_out;

    cudaFuncSetAttribute(k_step, cudaFuncAttributeMaxDynamicSharedMemorySize, STEP_SMEM);

    k_init<<<256, 256>>>(h_in, msg_in, sw1, sw2, mw1, mw2);
    k_mod<<<NN, 256>>>(h_in, heb, declog, prim_in, wconn,
                       modw1, modb1, modw2, modb2, nid);
    k_const<<<dim3(512, 2), 256>>>(sb1, mb1, nid);

    for (int t = 0; t < TT; ++t) {
        k_step<<<dim3(NN/64, BSZ), 128, STEP_SMEM>>>(t, cc, conn, nid, sb2, mb2, out);
    }
}

// round 15
// speedup vs baseline: 1.0309x; 1.0309x over previous
#include <cuda_runtime.h>
#include <math.h>
#include <stdint.h>

#define NN   4096
#define KK   32
#define DD   64
#define BSZ  8
#define TT   32
#define HSZ  256
#define ROWS (BSZ*NN)

typedef unsigned long long u64;

// ================= persistent device scratch =================
__device__ float4 g_wsig4[ROWS*KK/4];
__device__ float  g_d[ROWS];
__device__ float  g_dec[ROWS];
__device__ float  g_prim[ROWS*DD];
__device__ float  g_sconst[(size_t)ROWS*HSZ];   // [row][256]
__device__ float  g_mconst[(size_t)ROWS*HSZ];
__device__ float2 g_h2[ROWS*DD/2];              // [row][32 float2]
__device__ float2 g_msg2[2][ROWS*DD/2];
__device__ float  g_WsC[129*HSZ];               // const-GEMM weights [j][h]
__device__ float  g_WmC[129*HSZ];
// fragment-packed bf16 weights: phase p*4096 .. : uint4 = {b0h,b1h,b0l,b1l}
// p0 = Wsi (wide 64x256), p1 = Ws2 (narrow 256x64), p2 = Wmh, p3 = Wm2
__device__ uint4  g_Wpk[4*4096];

// ================= helpers =================
__device__ __forceinline__ float ftanh(float x) {
    float ax = fabsf(x);
    float e  = __expf(-2.f*ax);
    float t  = __fdividef(1.f - e, 1.f + e);
    return copysignf(t, x);
}
__device__ __forceinline__ float fsigmoid(float x) {
    return __fdividef(1.f, 1.f + __expf(-x));
}
__device__ __forceinline__ u64 pack2(float x) {
    u64 r; unsigned xi = __float_as_uint(x);
    asm("mov.b64 %0, {%1,%1};" : "=l"(r) : "r"(xi));
    return r;
}
__device__ __forceinline__ float2 unpack2(u64 v) {
    unsigned lo, hi;
    asm("mov.b64 {%0,%1}, %2;" : "=r"(lo), "=r"(hi) : "l"(v));
    return make_float2(__uint_as_float(lo), __uint_as_float(hi));
}
__device__ __forceinline__ void ffma2(u64& d, u64 a, u64 b) {
    asm("fma.rn.f32x2 %0, %1, %2, %0;" : "+l"(d) : "l"(a), "l"(b));
}
// split (a,b) into bf16 hi-pair and lo-pair; lower 16 bits = a
__device__ __forceinline__ void split2(float a, float b, uint32_t& hi, uint32_t& lo) {
    uint32_t h;
    asm("cvt.rn.bf16x2.f32 %0, %1, %2;" : "=r"(h) : "f"(b), "f"(a));
    float ra = a - __uint_as_float(h << 16);
    float rb = b - __uint_as_float(h & 0xffff0000u);
    uint32_t l;
    asm("cvt.rn.bf16x2.f32 %0, %1, %2;" : "=r"(l) : "f"(rb), "f"(ra));
    hi = h; lo = l;
}
__device__ __forceinline__ void ldm_x4(uint32_t* r, uint32_t addr) {
    asm volatile("ldmatrix.sync.aligned.m8n8.x4.shared.b16 {%0,%1,%2,%3}, [%4];"
        : "=r"(r[0]), "=r"(r[1]), "=r"(r[2]), "=r"(r[3]) : "r"(addr));
}
__device__ __forceinline__ void mma_bf16(float* d, const uint32_t* a,
                                         uint32_t b0, uint32_t b1) {
    asm volatile("mma.sync.aligned.m16n8k16.row.col.f32.bf16.bf16.f32 "
        "{%0,%1,%2,%3}, {%4,%5,%6,%7}, {%8,%9}, {%0,%1,%2,%3};"
        : "+f"(d[0]), "+f"(d[1]), "+f"(d[2]), "+f"(d[3])
        : "r"(a[0]), "r"(a[1]), "r"(a[2]), "r"(a[3]), "r"(b0), "r"(b1));
}
__device__ __forceinline__ uint32_t smem_u32(const void* p) {
    uint32_t a;
    asm("{ .reg .u64 t; cvta.to.shared.u64 t, %1; cvt.u32.u64 %0, t; }"
        : "=r"(a) : "l"(p));
    return a;
}
__device__ __forceinline__ void prefetch_l2(const void* p) {
    asm volatile("prefetch.global.L2 [%0];" :: "l"(p));
}

// ================= init: copy state, build const-W, pack mma weights =================
__global__ void k_init(const float* __restrict__ h_in, const float* __restrict__ msg_in,
                       const float* __restrict__ sw1, const float* __restrict__ sw2,
                       const float* __restrict__ mw1, const float* __restrict__ mw2)
{
    int i0 = blockIdx.x*blockDim.x + threadIdx.x;
    int stride = gridDim.x*blockDim.x;
    float* gh  = (float*)g_h2;
    float* gm0 = (float*)g_msg2[0];
    for (int i = i0; i < ROWS*DD; i += stride) { gh[i] = h_in[i]; gm0[i] = msg_in[i]; }
    for (int i = i0; i < 129*HSZ; i += stride) {
        int j = i >> 8, h = i & 255;
        g_WsC[i] = (j < 128) ? sw1[h*193 + 64 + j] : sw1[h*193 + 192];
        g_WmC[i] = (j < 128) ? mw1[h*192 + 64 + j] : 0.f;
    }
    for (int e = i0; e < 4*4096; e += stride) {
        int p = e >> 12, r = e & 4095;
        int lane = r & 31, q = r >> 5;
        int NT = (p == 0 || p == 2) ? 32 : 8;
        int kt = q / NT, nt = q - kt*NT;
        int k0 = kt*16 + (lane & 3)*2;
        int n  = nt*8 + (lane >> 2);
        float w00, w01, w10, w11;
        if (p == 0)      { const float* s = sw1 + (size_t)n*193;
                           w00 = s[k0]; w01 = s[k0+1]; w10 = s[k0+8]; w11 = s[k0+9]; }
        else if (p == 1) { const float* s = sw2 + (size_t)n*256;
                           w00 = s[k0]; w01 = s[k0+1]; w10 = s[k0+8]; w11 = s[k0+9]; }
        else if (p == 2) { const float* s = mw1 + (size_t)n*192;
                           w00 = s[k0]; w01 = s[k0+1]; w10 = s[k0+8]; w11 = s[k0+9]; }
        else             { const float* s = mw2 + (size_t)n*256;
                           w00 = s[k0]; w01 = s[k0+1]; w10 = s[k0+8]; w11 = s[k0+9]; }
        uint32_t b0h, b0l, b1h, b1l;
        split2(w00, w01, b0h, b0l);
        split2(w10, w11, b1h, b1l);
        g_Wpk[e] = make_uint4(b0h, b1h, b0l, b1l);
    }
}

// ================= per-neuron modulation MLP (unchanged) =================
__global__ void k_mod(const float* __restrict__ h_in, const float* __restrict__ heb,
                      const float* __restrict__ dec_in, const float* __restrict__ prim_in,
                      const float* __restrict__ wconn_in,
                      const float* __restrict__ mw1, const float* __restrict__ mb1,
                      const float* __restrict__ mw2, const float* __restrict__ mb2,
                      const float* __restrict__ nid)
{
    const int n = blockIdx.x;
    const int tid = threadIdx.x;
    const int warp = tid >> 5, lane = tid & 31;
    __shared__ float xs[BSZ*225];
    __shared__ float hid[BSZ*64];
    __shared__ float dlt[BSZ*97];

    for (int i = tid; i < BSZ*225; i += 256) {
        int b = i / 225, j = i - b*225;
        size_t bn = (size_t)b*NN + n;
        float v;
        if (j < 32)        v = heb[bn*32 + j];
        else if (j < 96)   v = h_in[bn*64 + (j-32)];
        else if (j == 96)  v = dec_in[bn];
        else if (j < 161)  v = prim_in[bn*64 + (j-97)];
        else               v = nid[(size_t)n*64 + (j-161)];
        xs[i] = v;
    }
    __syncthreads();

    const float* w1 = mw1 + (size_t)n*64*225;
    for (int hh = warp; hh < 64; hh += 8) {
        float acc[BSZ];
        #pragma unroll
        for (int b = 0; b < BSZ; b++) acc[b] = 0.f;
        for (int j = lane; j < 225; j += 32) {
            float w = w1[hh*225 + j];
            #pragma unroll
            for (int b = 0; b < BSZ; b++) acc[b] += w * xs[b*225 + j];
        }
        #pragma unroll
        for (int off = 16; off; off >>= 1) {
            #pragma unroll
            for (int b = 0; b < BSZ; b++) acc[b] += __shfl_xor_sync(0xffffffffu, acc[b], off);
        }
        if (lane == 0) {
            float bb = mb1[(size_t)n*64 + hh];
            #pragma unroll
            for (int b = 0; b < BSZ; b++) hid[b*64 + hh] = ftanh(acc[b] + bb);
        }
    }
    __syncthreads();

    const float* w2 = mw2 + (size_t)n*64*97;
    for (int o = warp; o < 97; o += 8) {
        float acc[BSZ];
        #pragma unroll
        for (int b = 0; b < BSZ; b++) acc[b] = 0.f;
        #pragma unroll
        for (int j2 = 0; j2 < 2; ++j2) {
            int j = lane + 32*j2;
            float w = w2[(size_t)j*97 + o];
            #pragma unroll
            for (int b = 0; b < BSZ; b++) acc[b] += w * hid[b*64 + j];
        }
        #pragma unroll
        for (int off = 16; off; off >>= 1) {
            #pragma unroll
            for (int b = 0; b < BSZ; b++) acc[b] += __shfl_xor_sync(0xffffffffu, acc[b], off);
        }
        if (lane == 0) {
            float bb = mb2[(size_t)n*97 + o];
            #pragma unroll
            for (int b = 0; b < BSZ; b++) dlt[b*97 + o] = acc[b] + bb;
        }
    }
    __syncthreads();

    float* wsig = (float*)g_wsig4;
    for (int i = tid; i < BSZ*KK; i += 256) {
        int b = i >> 5, k = i & 31;
        size_t bn = (size_t)b*NN + n;
        wsig[bn*32 + k] = fsigmoid(wconn_in[bn*32 + k] + dlt[b*97 + k]);
    }
    if (tid < BSZ) {
        size_t bn = (size_t)tid*NN + n;
        float v = dec_in[bn] + dlt[tid*97 + 32];
        g_dec[bn] = v;
        g_d[bn] = fsigmoid(v);
    }
    if (warp < BSZ) {
        int b = warp;
        size_t bn = (size_t)b*NN + n;
        float p0 = prim_in[bn*64 + lane]      + dlt[b*97 + 33 + lane];
        float p1 = prim_in[bn*64 + lane + 32] + dlt[b*97 + 33 + lane + 32];
        float ss = p0*p0 + p1*p1;
        #pragma unroll
        for (int off = 16; off; off >>= 1) ss += __shfl_xor_sync(0xffffffffu, ss, off);
        float sc = rsqrtf(ss*(1.f/64.f) + 1e-6f);
        g_prim[bn*64 + lane]      = p0*sc;
        g_prim[bn*64 + lane + 32] = p1*sc;
    }
}

// ================= state_const / msg_const (unchanged) =================
__global__ __launch_bounds__(256, 4)
void k_const(const float* __restrict__ sb1, const float* __restrict__ mb1_,
             const float* __restrict__ nid)
{
    __shared__ float xs[64*132];
    const int tid = threadIdx.x;
    const int r0 = blockIdx.x * 64;
    const int which = blockIdx.y;
    const float* WC = which ? g_WsC : g_WmC;
    const float* b1 = which ? sb1 : mb1_;
    float* outp     = which ? g_sconst : g_mconst;

    for (int i = tid; i < 64*132; i += 256) {
        int rr = i / 132, j = i - rr*132;
        size_t r = (size_t)(r0 + rr);
        int nn_ = (int)(r & (NN-1));
        float v = 0.f;
        if (j < 64)        v = g_prim[r*64 + j];
        else if (j < 128)  v = nid[(size_t)nn_*64 + (j-64)];
        else if (j == 128) v = g_dec[r];
        xs[i] = v;
    }
    __syncthreads();

    const int ty = tid >> 5, tx = tid & 31;
    float acc[8][8];
    #pragma unroll
    for (int i = 0; i < 8; i++)
        #pragma unroll
        for (int u = 0; u < 8; u++) acc[i][u] = 0.f;
    for (int j = 0; j < 129; ++j) {
        float a[8], w[8];
        #pragma unroll
        for (int i = 0; i < 8; i++) a[i] = xs[(ty*8+i)*132 + j];
        #pragma unroll
        for (int u = 0; u < 8; u++) w[u] = __ldg(WC + j*256 + tx + 32*u);
        #pragma unroll
        for (int i = 0; i < 8; i++)
            #pragma unroll
            for (int u = 0; u < 8; u++) acc[i][u] += a[i]*w[u];
    }
    #pragma unroll
    for (int i = 0; i < 8; i++) {
        int r = r0 + ty*8 + i;
        #pragma unroll
        for (int u = 0; u < 8; u++) {
            int c = tx + 32*u;
            outp[(size_t)r*256 + c] = acc[i][u] + __ldg(b1 + c);
        }
    }
}

// ================= pipelined fused wide->tanh->narrow (registers only) =================
__device__ __forceinline__ void wide_mma(
    const uint32_t A0[4][4], const uint32_t A1[4][4],
    const uint4* __restrict__ Wwide, const float* __restrict__ cst,
    int kt, int ln, int gr, int q, float d[2][2][4], float2 cc_[2][2])
{
    #pragma unroll
    for (int half = 0; half < 2; ++half) {
        const int nt = 2*kt + half;
        #pragma unroll
        for (int s = 0; s < 2; ++s)
            #pragma unroll
            for (int i = 0; i < 4; ++i) d[half][s][i] = 0.f;
        #pragma unroll
        for (int wk = 0; wk < 4; ++wk) {
            uint4 u = __ldg(Wwide + (size_t)(wk*32 + nt)*32 + ln);
            mma_bf16(d[half][0], A0[wk], u.x, u.y);   // chain depth 4
            mma_bf16(d[half][1], A0[wk], u.z, u.w);   // chain depth 8
            mma_bf16(d[half][1], A1[wk], u.x, u.y);
        }
        const int c0 = nt*8 + q*2;
        cc_[half][0] = *(const float2*)(cst + (size_t)gr*256 + c0);
        cc_[half][1] = *(const float2*)(cst + (size_t)(gr+8)*256 + c0);
    }
}

__device__ __forceinline__ void wide_epi(const float d[2][2][4], const float2 cc_[2][2],
                                         uint32_t ah[4], uint32_t al[4])
{
    #pragma unroll
    for (int half = 0; half < 2; ++half) {
        float h0 = ftanh(d[half][0][0] + d[half][1][0] + cc_[half][0].x);
        float h1 = ftanh(d[half][0][1] + d[half][1][1] + cc_[half][0].y);
        float h2 = ftanh(d[half][0][2] + d[half][1][2] + cc_[half][1].x);
        float h3 = ftanh(d[half][0][3] + d[half][1][3] + cc_[half][1].y);
        split2(h0, h1, ah[half*2],   al[half*2]);
        split2(h2, h3, ah[half*2+1], al[half*2+1]);
    }
}

__device__ __forceinline__ void narrow_step(const uint32_t ah[4], const uint32_t al[4],
                                            const uint4* __restrict__ Wn, int kt, int ln,
                                            float nacc[8][4])
{
    #pragma unroll
    for (int nt = 0; nt < 8; ++nt) {
        uint4 u = __ldg(Wn + (size_t)(kt*8 + nt)*32 + ln);
        mma_bf16(nacc[nt], ah, u.x, u.y);
        mma_bf16(nacc[nt], ah, u.z, u.w);
        mma_bf16(nacc[nt], al, u.x, u.y);
    }
}

__device__ __forceinline__ void fused_wide_narrow(
    const uint32_t Ah[4][4], const uint32_t Al[4][4],
    const uint4* __restrict__ Wwide, const uint4* __restrict__ Wnarrow,
    const float* __restrict__ cst, int ln, float nacc[8][4])
{
    const int gr = ln >> 2, q = ln & 3;
    #pragma unroll
    for (int nt = 0; nt < 8; nt++)
        #pragma unroll
        for (int i = 0; i < 4; i++) nacc[nt][i] = 0.f;

    float d[2][2][4]; float2 cc_[2][2];
    uint32_t ah[4], al[4];
    wide_mma(Ah, Al, Wwide, cst, 0, ln, gr, q, d, cc_);
    wide_epi(d, cc_, ah, al);
    #pragma unroll 1
    for (int kt = 1; kt < 16; ++kt) {
        float d2[2][2][4]; float2 cc2[2][2];
        wide_mma(Ah, Al, Wwide, cst, kt, ln, gr, q, d2, cc2);  // fills pipe
        narrow_step(ah, al, Wnarrow, kt-1, ln, nacc);          // overlaps wide latency
        wide_epi(d2, cc2, ah, al);
    }
    narrow_step(ah, al, Wnarrow, 15, ln, nacc);
}

// ================= fused step: gather -> (wide+narrow)x2, register-chained =================
#define A_STRIDE   144
#define AH_OFF     0
#define AL_OFF     2304
#define WARP_BYTES 4608
#define STEP_SMEM  (4*WARP_BYTES)

__global__ __launch_bounds__(128, 4)
void k_step(int t, const float* __restrict__ cc, const int* __restrict__ conn,
            const float* __restrict__ nid, const float* __restrict__ sb2,
            const float* __restrict__ mb2, float* __restrict__ out)
{
    extern __shared__ char smem[];
    const int tid = threadIdx.x;
    const int w   = tid >> 5, ln = tid & 31;
    char*    wmem = smem + w*WARP_BYTES;
    const uint32_t wsm = smem_u32(smem) + w*WARP_BYTES;

    const int b      = blockIdx.y;
    const int ntblk  = blockIdx.x;
    const int n0     = ntblk*64;
    const int nfirst = n0 + w*16;
    const int sel    = t & 1;
    const size_t growbase = (size_t)b*NN + nfirst;

    // prefetch this CTA's sconst rows into L2 (covered by gather phase)
    {
        const float* sc = g_sconst + ((size_t)b*NN + n0)*256;
        #pragma unroll
        for (int k = 0; k < 4; ++k)
            prefetch_l2(sc + (size_t)(tid + k*128)*32);
    }

    // ---- phase 0: gather (+inject) -> bf16 h/l A-tile in smem ----
    {
        const u64*    mq  = (const u64*)g_msg2[sel] + (size_t)b*NN*32;
        const int4*   cn4 = (const int4*)conn;
        const float4* ws4 = (const float4*)g_wsig4;
        #pragma unroll 1
        for (int g = 0; g < 16; ++g) {
            const int n = nfirst + g;
            const size_t cb = (size_t)n*8;
            const size_t wb = ((size_t)b*NN + n)*8;
            u64 a0 = 0ull, a1 = 0ull;
            #pragma unroll
            for (int kq = 0; kq < 8; ++kq) {
                int4   id = __ldg(cn4 + cb + kq);
                float4 wt = __ldg(ws4 + wb + kq);
                ffma2(a0, pack2(wt.x), mq[(size_t)id.x*32 + ln]);
                ffma2(a1, pack2(wt.y), mq[(size_t)id.y*32 + ln]);
                ffma2(a0, pack2(wt.z), mq[(size_t)id.z*32 + ln]);
                ffma2(a1, pack2(wt.w), mq[(size_t)id.w*32 + ln]);
            }
            float2 v0 = unpack2(a0), v1 = unpack2(a1);
            float x0 = v0.x + v1.x, x1 = v0.y + v1.y;
            if ((n & 127) < 4) {
                float2 cv = *(const float2*)(cc + ((size_t)b*TT + t)*2048 + (n>>7)*64 + ln*2);
                x0 += cv.x; x1 += cv.y;
            }
            uint32_t hi, lo;
            split2(x0, x1, hi, lo);
            *(uint32_t*)(wmem + AH_OFF + g*A_STRIDE + ln*4) = hi;
            *(uint32_t*)(wmem + AL_OFF + g*A_STRIDE + ln*4) = lo;
        }
    }
    __syncwarp();

    // prefetch mconst rows into L2 (covered by fused call 1)
    {
        const float* mc = g_mconst + ((size_t)b*NN + n0)*256;
        #pragma unroll
        for (int k = 0; k < 4; ++k)
            prefetch_l2(mc + (size_t)(tid + k*128)*32);
    }

    // load gather A-frags once; smem A region free afterwards.
    // These SAME registers are reused for the phase-3 A-fragments (h).
    uint32_t Ah[4][4], Al[4][4];
    {
        const int row = ln & 15;
        const uint32_t coff = (uint32_t)((ln >> 4) << 4);
        #pragma unroll
        for (int kt = 0; kt < 4; kt++) {
            uint32_t ad = wsm + AH_OFF + row*A_STRIDE + kt*32 + coff;
            ldm_x4(Ah[kt], ad);
            ldm_x4(Al[kt], ad + (AL_OFF - AH_OFF));
        }
    }
    __syncwarp();

    const int gr = ln >> 2, q = ln & 3;
    float nacc[8][4];

    // ---- phases 1+2: hid = tanh(recv@Wsi + sconst); nacc = hid@Ws2 ----
    fused_wide_narrow(Ah, Al, g_Wpk, g_Wpk + 4096,
                      g_sconst + growbase*256, ln, nacc);

    // ---- phase 2 epilogue: h update; OVERWRITE Ah/Al with phase-3 A-frags ----
    {
        const float dv0 = g_d[growbase + gr];
        const float dv1 = g_d[growbase + gr + 8];
        #pragma unroll
        for (int nt = 0; nt < 8; ++nt) {
            const int c0 = nt*8 + q*2;
            float2 bb = *(const float2*)(sb2 + c0);
            // row gr
            {
                float2 ho = g_h2[(growbase + gr)*32 + (c0 >> 1)];
                float u0 = ftanh(nacc[nt][0] + bb.x), u1 = ftanh(nacc[nt][1] + bb.y);
                float hv0 = dv0*ho.x + (1.f-dv0)*u0, hv1 = dv0*ho.y + (1.f-dv0)*u1;
                g_h2[(growbase + gr)*32 + (c0 >> 1)] = make_float2(hv0, hv1);
                split2(hv0, hv1, Ah[nt>>1][(nt&1)*2], Al[nt>>1][(nt&1)*2]);
            }
            // row gr+8
            {
                float2 ho = g_h2[(growbase + gr + 8)*32 + (c0 >> 1)];
                float u0 = ftanh(nacc[nt][2] + bb.x), u1 = ftanh(nacc[nt][3] + bb.y);
                float hv0 = dv1*ho.x + (1.f-dv1)*u0, hv1 = dv1*ho.y + (1.f-dv1)*u1;
                g_h2[(growbase + gr + 8)*32 + (c0 >> 1)] = make_float2(hv0, hv1);
                split2(hv0, hv1, Ah[nt>>1][(nt&1)*2+1], Al[nt>>1][(nt&1)*2+1]);
            }
        }
    }

    // ---- phases 3+4: mh = tanh(h@Wmh + mconst); nacc = mh@Wm2 ----
    fused_wide_narrow(Ah, Al, g_Wpk + 2*4096, g_Wpk + 3*4096,
                      g_mconst + growbase*256, ln, nacc);

    // ---- phase 4 epilogue: msg = tanh(.+mb2)+nid; readout ----
    {
        const int roflag = (ntblk & 1) && (w == 3);
        float2* msgout = g_msg2[sel ^ 1];
        float* s_ro = (float*)wmem;      // gather A region, free now
        #pragma unroll
        for (int nt = 0; nt < 8; ++nt) {
            const int c0 = nt*8 + q*2;
            float2 bb = *(const float2*)(mb2 + c0);
            // row gr
            {
                int n = nfirst + gr;
                size_t grow = growbase + gr;
                float2 nv = *(const float2*)(nid + (size_t)n*64 + c0);
                float m0 = ftanh(nacc[nt][0] + bb.x) + nv.x;
                float m1 = ftanh(nacc[nt][1] + bb.y) + nv.y;
                msgout[grow*32 + (c0 >> 1)] = make_float2(m0, m1);
            }
            // row gr+8
            {
                int n = nfirst + gr + 8;
                size_t grow = growbase + gr + 8;
                float2 nv = *(const float2*)(nid + (size_t)n*64 + c0);
                float m0 = ftanh(nacc[nt][2] + bb.x) + nv.x;
                float m1 = ftanh(nacc[nt][3] + bb.y) + nv.y;
                msgout[grow*32 + (c0 >> 1)] = make_float2(m0, m1);
                if (roflag && gr >= 4)
                    *(float2*)(s_ro + (gr-4)*64 + c0) = make_float2(m0, m1);
            }
        }
        __syncwarp();
        if (roflag) {
            size_t obase = ((size_t)b*TT + t)*2048 + (ntblk >> 1)*64;
            float v0 = 0.25f*(s_ro[ln]      + s_ro[64+ln]  + s_ro[128+ln] + s_ro[192+ln]);
            float v1 = 0.25f*(s_ro[32+ln]   + s_ro[96+ln]  + s_ro[160+ln] + s_ro[224+ln]);
            out[obase + ln]      = v0;
            out[obase + 32 + ln] = v1;
        }
    }
}

// ================= launcher =================
extern "C" void kernel_launch(void* const* d_in, const int* in_sizes, int n_in,
                              void* d_out, int out_size)
{
    const float* cc      = (const float*)d_in[0];
    const float* h_in    = (const float*)d_in[1];
    const float* msg_in  = (const float*)d_in[2];
    const float* wconn   = (const float*)d_in[3];
    const float* declog  = (const float*)d_in[4];
    const float* prim_in = (const float*)d_in[5];
    const float* heb     = (const float*)d_in[6];
    const float* sw1     = (const float*)d_in[7];
    const float* sb1     = (const float*)d_in[8];
    const float* sw2     = (const float*)d_in[9];
    const float* sb2     = (const float*)d_in[10];
    const float* mw1     = (const float*)d_in[11];
    const float* mb1     = (const float*)d_in[12];
    const float* mw2     = (const float*)d_in[13];
    const float* mb2     = (const float*)d_in[14];
    const float* modw1   = (const float*)d_in[15];
    const float* modb1   = (const float*)d_in[16];
    const float* modw2   = (const float*)d_in[17];
    const float* modb2   = (const float*)d_in[18];
    const float* nid     = (const float*)d_in[19];
    const int*   conn    = (const int*)d_in[20];
    float* out = (float*)d_out;

    cudaFuncSetAttribute(k_step, cudaFuncAttributeMaxDynamicSharedMemorySize, STEP_SMEM);

    k_init<<<256, 256>>>(h_in, msg_in, sw1, sw2, mw1, mw2);
    k_mod<<<NN, 256>>>(h_in, heb, declog, prim_in, wconn,
                       modw1, modb1, modw2, modb2, nid);
    k_const<<<dim3(512, 2), 256>>>(sb1, mb1, nid);

    for (int t = 0; t < TT; ++t) {
        k_step<<<dim3(NN/64, BSZ), 128, STEP_SMEM>>>(t, cc, conn, nid, sb2, mb2, out);
    }
}

// round 17
// speedup vs baseline: 1.0580x; 1.0263x over previous
#include <cuda_runtime.h>
#include <math.h>
#include <stdint.h>

#define NN   4096
#define KK   32
#define DD   64
#define BSZ  8
#define TT   32
#define HSZ  256
#define ROWS (BSZ*NN)

typedef unsigned long long u64;

// ================= persistent device scratch =================
__device__ float4 g_wsig4[ROWS*KK/4];
__device__ float  g_d[ROWS];
__device__ float  g_dec[ROWS];
__device__ float  g_prim[ROWS*DD];
__device__ float  g_sconst[(size_t)ROWS*HSZ];   // [row][256]
__device__ float  g_mconst[(size_t)ROWS*HSZ];
__device__ float2 g_h2[ROWS*DD/2];              // [row][32 float2]
__device__ float2 g_msg2[2][ROWS*DD/2];
__device__ float  g_WsC[129*HSZ];               // const-GEMM weights [j][h]
__device__ float  g_WmC[129*HSZ];
// fragment-packed bf16 weights: phase p*4096 : uint4 = {b0h,b1h,b0l,b1l}
// p0 = Wsi (wide 64x256), p1 = Ws2 (narrow 256x64), p2 = Wmh, p3 = Wm2
__device__ uint4  g_Wpk[4*4096];
// narrow weights split into hi/lo planes (term-major passes): 0 = Ws2, 1 = Wm2
__device__ uint2  g_WnH[2*4096];
__device__ uint2  g_WnL[2*4096];

// ================= helpers =================
__device__ __forceinline__ float ftanh(float x) {
    float ax = fabsf(x);
    float e  = __expf(-2.f*ax);
    float t  = __fdividef(1.f - e, 1.f + e);
    return copysignf(t, x);
}
__device__ __forceinline__ float fsigmoid(float x) {
    return __fdividef(1.f, 1.f + __expf(-x));
}
__device__ __forceinline__ u64 pack2(float x) {
    u64 r; unsigned xi = __float_as_uint(x);
    asm("mov.b64 %0, {%1,%1};" : "=l"(r) : "r"(xi));
    return r;
}
__device__ __forceinline__ float2 unpack2(u64 v) {
    unsigned lo, hi;
    asm("mov.b64 {%0,%1}, %2;" : "=r"(lo), "=r"(hi) : "l"(v));
    return make_float2(__uint_as_float(lo), __uint_as_float(hi));
}
__device__ __forceinline__ void ffma2(u64& d, u64 a, u64 b) {
    asm("fma.rn.f32x2 %0, %1, %2, %0;" : "+l"(d) : "l"(a), "l"(b));
}
// split (a,b) into bf16 hi-pair and lo-pair; lower 16 bits = a
__device__ __forceinline__ void split2(float a, float b, uint32_t& hi, uint32_t& lo) {
    uint32_t h;
    asm("cvt.rn.bf16x2.f32 %0, %1, %2;" : "=r"(h) : "f"(b), "f"(a));
    float ra = a - __uint_as_float(h << 16);
    float rb = b - __uint_as_float(h & 0xffff0000u);
    uint32_t l;
    asm("cvt.rn.bf16x2.f32 %0, %1, %2;" : "=r"(l) : "f"(rb), "f"(ra));
    hi = h; lo = l;
}
__device__ __forceinline__ void ldm_x4(uint32_t* r, uint32_t addr) {
    asm volatile("ldmatrix.sync.aligned.m8n8.x4.shared.b16 {%0,%1,%2,%3}, [%4];"
        : "=r"(r[0]), "=r"(r[1]), "=r"(r[2]), "=r"(r[3]) : "r"(addr));
}
__device__ __forceinline__ void mma_bf16(float* d, const uint32_t* a,
                                         uint32_t b0, uint32_t b1) {
    asm volatile("mma.sync.aligned.m16n8k16.row.col.f32.bf16.bf16.f32 "
        "{%0,%1,%2,%3}, {%4,%5,%6,%7}, {%8,%9}, {%0,%1,%2,%3};"
        : "+f"(d[0]), "+f"(d[1]), "+f"(d[2]), "+f"(d[3])
        : "r"(a[0]), "r"(a[1]), "r"(a[2]), "r"(a[3]), "r"(b0), "r"(b1));
}
__device__ __forceinline__ uint32_t smem_u32(const void* p) {
    uint32_t a;
    asm("{ .reg .u64 t; cvta.to.shared.u64 t, %1; cvt.u32.u64 %0, t; }"
        : "=r"(a) : "l"(p));
    return a;
}

// ================= init: copy state, build const-W, pack mma weights =================
__global__ void k_init(const float* __restrict__ h_in, const float* __restrict__ msg_in,
                       const float* __restrict__ sw1, const float* __restrict__ sw2,
                       const float* __restrict__ mw1, const float* __restrict__ mw2)
{
    int i0 = blockIdx.x*blockDim.x + threadIdx.x;
    int stride = gridDim.x*blockDim.x;
    float* gh  = (float*)g_h2;
    float* gm0 = (float*)g_msg2[0];
    for (int i = i0; i < ROWS*DD; i += stride) { gh[i] = h_in[i]; gm0[i] = msg_in[i]; }
    for (int i = i0; i < 129*HSZ; i += stride) {
        int j = i >> 8, h = i & 255;
        g_WsC[i] = (j < 128) ? sw1[h*193 + 64 + j] : sw1[h*193 + 192];
        g_WmC[i] = (j < 128) ? mw1[h*192 + 64 + j] : 0.f;
    }
    for (int e = i0; e < 4*4096; e += stride) {
        int p = e >> 12, r = e & 4095;
        int lane = r & 31, q = r >> 5;
        int NT = (p == 0 || p == 2) ? 32 : 8;
        int kt = q / NT, nt = q - kt*NT;
        int k0 = kt*16 + (lane & 3)*2;
        int n  = nt*8 + (lane >> 2);
        float w00, w01, w10, w11;
        if (p == 0)      { const float* s = sw1 + (size_t)n*193;
                           w00 = s[k0]; w01 = s[k0+1]; w10 = s[k0+8]; w11 = s[k0+9]; }
        else if (p == 1) { const float* s = sw2 + (size_t)n*256;
                           w00 = s[k0]; w01 = s[k0+1]; w10 = s[k0+8]; w11 = s[k0+9]; }
        else if (p == 2) { const float* s = mw1 + (size_t)n*192;
                           w00 = s[k0]; w01 = s[k0+1]; w10 = s[k0+8]; w11 = s[k0+9]; }
        else             { const float* s = mw2 + (size_t)n*256;
                           w00 = s[k0]; w01 = s[k0+1]; w10 = s[k0+8]; w11 = s[k0+9]; }
        uint32_t b0h, b0l, b1h, b1l;
        split2(w00, w01, b0h, b0l);
        split2(w10, w11, b1h, b1l);
        g_Wpk[e] = make_uint4(b0h, b1h, b0l, b1l);
        if (p == 1 || p == 3) {
            int pn = (p == 1) ? 0 : 1;
            g_WnH[pn*4096 + r] = make_uint2(b0h, b1h);
            g_WnL[pn*4096 + r] = make_uint2(b0l, b1l);
        }
    }
}

// ================= per-neuron modulation MLP (unchanged) =================
__global__ void k_mod(const float* __restrict__ h_in, const float* __restrict__ heb,
                      const float* __restrict__ dec_in, const float* __restrict__ prim_in,
                      const float* __restrict__ wconn_in,
                      const float* __restrict__ mw1, const float* __restrict__ mb1,
                      const float* __restrict__ mw2, const float* __restrict__ mb2,
                      const float* __restrict__ nid)
{
    const int n = blockIdx.x;
    const int tid = threadIdx.x;
    const int warp = tid >> 5, lane = tid & 31;
    __shared__ float xs[BSZ*225];
    __shared__ float hid[BSZ*64];
    __shared__ float dlt[BSZ*97];

    for (int i = tid; i < BSZ*225; i += 256) {
        int b = i / 225, j = i - b*225;
        size_t bn = (size_t)b*NN + n;
        float v;
        if (j < 32)        v = heb[bn*32 + j];
        else if (j < 96)   v = h_in[bn*64 + (j-32)];
        else if (j == 96)  v = dec_in[bn];
        else if (j < 161)  v = prim_in[bn*64 + (j-97)];
        else               v = nid[(size_t)n*64 + (j-161)];
        xs[i] = v;
    }
    __syncthreads();

    const float* w1 = mw1 + (size_t)n*64*225;
    for (int hh = warp; hh < 64; hh += 8) {
        float acc[BSZ];
        #pragma unroll
        for (int b = 0; b < BSZ; b++) acc[b] = 0.f;
        for (int j = lane; j < 225; j += 32) {
            float w = w1[hh*225 + j];
            #pragma unroll
            for (int b = 0; b < BSZ; b++) acc[b] += w * xs[b*225 + j];
        }
        #pragma unroll
        for (int off = 16; off; off >>= 1) {
            #pragma unroll
            for (int b = 0; b < BSZ; b++) acc[b] += __shfl_xor_sync(0xffffffffu, acc[b], off);
        }
        if (lane == 0) {
            float bb = mb1[(size_t)n*64 + hh];
            #pragma unroll
            for (int b = 0; b < BSZ; b++) hid[b*64 + hh] = ftanh(acc[b] + bb);
        }
    }
    __syncthreads();

    const float* w2 = mw2 + (size_t)n*64*97;
    for (int o = warp; o < 97; o += 8) {
        float acc[BSZ];
        #pragma unroll
        for (int b = 0; b < BSZ; b++) acc[b] = 0.f;
        #pragma unroll
        for (int j2 = 0; j2 < 2; ++j2) {
            int j = lane + 32*j2;
            float w = w2[(size_t)j*97 + o];
            #pragma unroll
            for (int b = 0; b < BSZ; b++) acc[b] += w * hid[b*64 + j];
        }
        #pragma unroll
        for (int off = 16; off; off >>= 1) {
            #pragma unroll
            for (int b = 0; b < BSZ; b++) acc[b] += __shfl_xor_sync(0xffffffffu, acc[b], off);
        }
        if (lane == 0) {
            float bb = mb2[(size_t)n*97 + o];
            #pragma unroll
            for (int b = 0; b < BSZ; b++) dlt[b*97 + o] = acc[b] + bb;
        }
    }
    __syncthreads();

    float* wsig = (float*)g_wsig4;
    for (int i = tid; i < BSZ*KK; i += 256) {
        int b = i >> 5, k = i & 31;
        size_t bn = (size_t)b*NN + n;
        wsig[bn*32 + k] = fsigmoid(wconn_in[bn*32 + k] + dlt[b*97 + k]);
    }
    if (tid < BSZ) {
        size_t bn = (size_t)tid*NN + n;
        float v = dec_in[bn] + dlt[tid*97 + 32];
        g_dec[bn] = v;
        g_d[bn] = fsigmoid(v);
    }
    if (warp < BSZ) {
        int b = warp;
        size_t bn = (size_t)b*NN + n;
        float p0 = prim_in[bn*64 + lane]      + dlt[b*97 + 33 + lane];
        float p1 = prim_in[bn*64 + lane + 32] + dlt[b*97 + 33 + lane + 32];
        float ss = p0*p0 + p1*p1;
        #pragma unroll
        for (int off = 16; off; off >>= 1) ss += __shfl_xor_sync(0xffffffffu, ss, off);
        float sc = rsqrtf(ss*(1.f/64.f) + 1e-6f);
        g_prim[bn*64 + lane]      = p0*sc;
        g_prim[bn*64 + lane + 32] = p1*sc;
    }
}

// ================= state_const / msg_const (unchanged) =================
__global__ __launch_bounds__(256, 4)
void k_const(const float* __restrict__ sb1, const float* __restrict__ mb1_,
             const float* __restrict__ nid)
{
    __shared__ float xs[64*132];
    const int tid = threadIdx.x;
    const int r0 = blockIdx.x * 64;
    const int which = blockIdx.y;
    const float* WC = which ? g_WsC : g_WmC;
    const float* b1 = which ? sb1 : mb1_;
    float* outp     = which ? g_sconst : g_mconst;

    for (int i = tid; i < 64*132; i += 256) {
        int rr = i / 132, j = i - rr*132;
        size_t r = (size_t)(r0 + rr);
        int nn_ = (int)(r & (NN-1));
        float v = 0.f;
        if (j < 64)        v = g_prim[r*64 + j];
        else if (j < 128)  v = nid[(size_t)nn_*64 + (j-64)];
        else if (j == 128) v = g_dec[r];
        xs[i] = v;
    }
    __syncthreads();

    const int ty = tid >> 5, tx = tid & 31;
    float acc[8][8];
    #pragma unroll
    for (int i = 0; i < 8; i++)
        #pragma unroll
        for (int u = 0; u < 8; u++) acc[i][u] = 0.f;
    for (int j = 0; j < 129; ++j) {
        float a[8], w[8];
        #pragma unroll
        for (int i = 0; i < 8; i++) a[i] = xs[(ty*8+i)*132 + j];
        #pragma unroll
        for (int u = 0; u < 8; u++) w[u] = __ldg(WC + j*256 + tx + 32*u);
        #pragma unroll
        for (int i = 0; i < 8; i++)
            #pragma unroll
            for (int u = 0; u < 8; u++) acc[i][u] += a[i]*w[u];
    }
    #pragma unroll
    for (int i = 0; i < 8; i++) {
        int r = r0 + ty*8 + i;
        #pragma unroll
        for (int u = 0; u < 8; u++) {
            int c = tx + 32*u;
            outp[(size_t)r*256 + c] = acc[i][u] + __ldg(b1 + c);
        }
    }
}

// ================= pipelined fused wide->tanh->narrow (registers only) =================
// wide: 6 independent chains of depth 4 per kt (split accumulators)
__device__ __forceinline__ void wide_mma(
    const uint32_t A0[4][4], const uint32_t A1[4][4],
    const uint4* __restrict__ Wwide, const float* __restrict__ cst,
    int kt, int ln, int gr, int q, float d[2][3][4], float2 cc_[2][2])
{
    #pragma unroll
    for (int half = 0; half < 2; ++half) {
        const int nt = 2*kt + half;
        #pragma unroll
        for (int s = 0; s < 3; ++s)
            #pragma unroll
            for (int i = 0; i < 4; ++i) d[half][s][i] = 0.f;
        #pragma unroll
        for (int wk = 0; wk < 4; ++wk) {
            uint4 u = __ldg(Wwide + (size_t)(wk*32 + nt)*32 + ln);
            mma_bf16(d[half][0], A0[wk], u.x, u.y);   // independent chain (depth 4)
            mma_bf16(d[half][1], A0[wk], u.z, u.w);   // independent chain (depth 4)
            mma_bf16(d[half][2], A1[wk], u.x, u.y);   // independent chain (depth 4)
        }
        const int c0 = nt*8 + q*2;
        cc_[half][0] = *(const float2*)(cst + (size_t)gr*256 + c0);
        cc_[half][1] = *(const float2*)(cst + (size_t)(gr+8)*256 + c0);
    }
}

__device__ __forceinline__ void wide_epi(const float d[2][3][4], const float2 cc_[2][2],
                                         uint32_t ah[4], uint32_t al[4])
{
    #pragma unroll
    for (int half = 0; half < 2; ++half) {
        float h0 = ftanh(d[half][0][0] + d[half][1][0] + d[half][2][0] + cc_[half][0].x);
        float h1 = ftanh(d[half][0][1] + d[half][1][1] + d[half][2][1] + cc_[half][0].y);
        float h2 = ftanh(d[half][0][2] + d[half][1][2] + d[half][2][2] + cc_[half][1].x);
        float h3 = ftanh(d[half][0][3] + d[half][1][3] + d[half][2][3] + cc_[half][1].y);
        split2(h0, h1, ah[half*2],   al[half*2]);
        split2(h2, h3, ah[half*2+1], al[half*2+1]);
    }
}

// narrow: term-major passes -> dependency distance 8 on every nacc chain
__device__ __forceinline__ void narrow_step(const uint32_t ah[4], const uint32_t al[4],
                                            const uint2* __restrict__ WnH,
                                            const uint2* __restrict__ WnL,
                                            int kt, int ln, float nacc[8][4])
{
    const size_t base = (size_t)(kt*8)*32 + ln;
    #pragma unroll
    for (int nt = 0; nt < 8; ++nt) {
        uint2 u = __ldg(WnH + base + nt*32);
        mma_bf16(nacc[nt], ah, u.x, u.y);
    }
    #pragma unroll
    for (int nt = 0; nt < 8; ++nt) {
        uint2 u = __ldg(WnL + base + nt*32);
        mma_bf16(nacc[nt], ah, u.x, u.y);
    }
    #pragma unroll
    for (int nt = 0; nt < 8; ++nt) {
        uint2 u = __ldg(WnH + base + nt*32);
        mma_bf16(nacc[nt], al, u.x, u.y);
    }
}

__device__ __forceinline__ void fused_wide_narrow(
    const uint32_t Ah[4][4], const uint32_t Al[4][4],
    const uint4* __restrict__ Wwide,
    const uint2* __restrict__ WnH, const uint2* __restrict__ WnL,
    const float* __restrict__ cst, int ln, float nacc[8][4])
{
    const int gr = ln >> 2, q = ln & 3;
    #pragma unroll
    for (int nt = 0; nt < 8; nt++)
        #pragma unroll
        for (int i = 0; i < 4; i++) nacc[nt][i] = 0.f;

    float d[2][3][4]; float2 cc_[2][2];
    uint32_t ah[4], al[4];
    wide_mma(Ah, Al, Wwide, cst, 0, ln, gr, q, d, cc_);
    wide_epi(d, cc_, ah, al);
    #pragma unroll 1
    for (int kt = 1; kt < 16; ++kt) {
        float d2[2][3][4]; float2 cc2[2][2];
        wide_mma(Ah, Al, Wwide, cst, kt, ln, gr, q, d2, cc2);  // fills pipe
        narrow_step(ah, al, WnH, WnL, kt-1, ln, nacc);         // overlaps wide latency
        wide_epi(d2, cc2, ah, al);
    }
    narrow_step(ah, al, WnH, WnL, 15, ln, nacc);
}

// ================= fused step: gather -> (wide+narrow)x2, register-chained =================
#define A_STRIDE   144
#define AH_OFF     0
#define AL_OFF     2304
#define WARP_BYTES 4608
#define STEP_SMEM  (4*WARP_BYTES)

__global__ __launch_bounds__(128, 4)
void k_step(int t, const float* __restrict__ cc, const int* __restrict__ conn,
            const float* __restrict__ nid, const float* __restrict__ sb2,
            const float* __restrict__ mb2, float* __restrict__ out)
{
    extern __shared__ char smem[];
    const int tid = threadIdx.x;
    const int w   = tid >> 5, ln = tid & 31;
    char*    wmem = smem + w*WARP_BYTES;
    const uint32_t wsm = smem_u32(smem) + w*WARP_BYTES;

    const int b      = blockIdx.y;
    const int ntblk  = blockIdx.x;
    const int n0     = ntblk*64;
    const int nfirst = n0 + w*16;
    const int sel    = t & 1;
    const size_t growbase = (size_t)b*NN + nfirst;

    // ---- phase 0: gather (+inject) -> bf16 h/l A-tile in smem ----
    {
        const u64*    mq  = (const u64*)g_msg2[sel] + (size_t)b*NN*32;
        const int4*   cn4 = (const int4*)conn;
        const float4* ws4 = (const float4*)g_wsig4;
        #pragma unroll 1
        for (int g = 0; g < 16; ++g) {
            const int n = nfirst + g;
            const size_t cb = (size_t)n*8;
            const size_t wb = ((size_t)b*NN + n)*8;
            u64 a0 = 0ull, a1 = 0ull;
            #pragma unroll
            for (int kq = 0; kq < 8; ++kq) {
                int4   id = __ldg(cn4 + cb + kq);
                float4 wt = __ldg(ws4 + wb + kq);
                ffma2(a0, pack2(wt.x), mq[(size_t)id.x*32 + ln]);
                ffma2(a1, pack2(wt.y), mq[(size_t)id.y*32 + ln]);
                ffma2(a0, pack2(wt.z), mq[(size_t)id.z*32 + ln]);
                ffma2(a1, pack2(wt.w), mq[(size_t)id.w*32 + ln]);
            }
            float2 v0 = unpack2(a0), v1 = unpack2(a1);
            float x0 = v0.x + v1.x, x1 = v0.y + v1.y;
            if ((n & 127) < 4) {
                float2 cv = *(const float2*)(cc + ((size_t)b*TT + t)*2048 + (n>>7)*64 + ln*2);
                x0 += cv.x; x1 += cv.y;
            }
            uint32_t hi, lo;
            split2(x0, x1, hi, lo);
            *(uint32_t*)(wmem + AH_OFF + g*A_STRIDE + ln*4) = hi;
            *(uint32_t*)(wmem + AL_OFF + g*A_STRIDE + ln*4) = lo;
        }
    }
    __syncwarp();

    // load gather A-frags once; smem A region free afterwards.
    // These SAME registers are reused for the phase-3 A-fragments (h).
    uint32_t Ah[4][4], Al[4][4];
    {
        const int row = ln & 15;
        const uint32_t coff = (uint32_t)((ln >> 4) << 4);
        #pragma unroll
        for (int kt = 0; kt < 4; kt++) {
            uint32_t ad = wsm + AH_OFF + row*A_STRIDE + kt*32 + coff;
            ldm_x4(Ah[kt], ad);
            ldm_x4(Al[kt], ad + (AL_OFF - AH_OFF));
        }
    }
    __syncwarp();

    const int gr = ln >> 2, q = ln & 3;
    float nacc[8][4];

    // ---- phases 1+2: hid = tanh(recv@Wsi + sconst); nacc = hid@Ws2 ----
    fused_wide_narrow(Ah, Al, g_Wpk, g_WnH, g_WnL,
                      g_sconst + growbase*256, ln, nacc);

    // ---- phase 2 epilogue: h update; OVERWRITE Ah/Al with phase-3 A-frags ----
    {
        const float dv0 = g_d[growbase + gr];
        const float dv1 = g_d[growbase + gr + 8];
        float2 ho0[8], ho1[8];
        #pragma unroll
        for (int nt = 0; nt < 8; ++nt) {
            const int ci = (nt*8 + q*2) >> 1;
            ho0[nt] = g_h2[(growbase + gr)*32 + ci];
            ho1[nt] = g_h2[(growbase + gr + 8)*32 + ci];
        }
        #pragma unroll
        for (int nt = 0; nt < 8; ++nt) {
            const int c0 = nt*8 + q*2;
            float2 bb = *(const float2*)(sb2 + c0);
            // row gr
            {
                float u0 = ftanh(nacc[nt][0] + bb.x), u1 = ftanh(nacc[nt][1] + bb.y);
                float hv0 = dv0*ho0[nt].x + (1.f-dv0)*u0, hv1 = dv0*ho0[nt].y + (1.f-dv0)*u1;
                g_h2[(growbase + gr)*32 + (c0 >> 1)] = make_float2(hv0, hv1);
                split2(hv0, hv1, Ah[nt>>1][(nt&1)*2], Al[nt>>1][(nt&1)*2]);
            }
            // row gr+8
            {
                float u0 = ftanh(nacc[nt][2] + bb.x), u1 = ftanh(nacc[nt][3] + bb.y);
                float hv0 = dv1*ho1[nt].x + (1.f-dv1)*u0, hv1 = dv1*ho1[nt].y + (1.f-dv1)*u1;
                g_h2[(growbase + gr + 8)*32 + (c0 >> 1)] = make_float2(hv0, hv1);
                split2(hv0, hv1, Ah[nt>>1][(nt&1)*2+1], Al[nt>>1][(nt&1)*2+1]);
            }
        }
    }

    // ---- phases 3+4: mh = tanh(h@Wmh + mconst); nacc = mh@Wm2 ----
    fused_wide_narrow(Ah, Al, g_Wpk + 2*4096, g_WnH + 4096, g_WnL + 4096,
                      g_mconst + growbase*256, ln, nacc);

    // ---- phase 4 epilogue: msg = tanh(.+mb2)+nid; readout ----
    {
        const int roflag = (ntblk & 1) && (w == 3);
        float2* msgout = g_msg2[sel ^ 1];
        float* s_ro = (float*)wmem;      // gather A region, free now
        #pragma unroll
        for (int nt = 0; nt < 8; ++nt) {
            const int c0 = nt*8 + q*2;
            float2 bb = *(const float2*)(mb2 + c0);
            // row gr
            {
                int n = nfirst + gr;
                size_t grow = growbase + gr;
                float2 nv = *(const float2*)(nid + (size_t)n*64 + c0);
                float m0 = ftanh(nacc[nt][0] + bb.x) + nv.x;
                float m1 = ftanh(nacc[nt][1] + bb.y) + nv.y;
                msgout[grow*32 + (c0 >> 1)] = make_float2(m0, m1);
            }
            // row gr+8
            {
                int n = nfirst + gr + 8;
                size_t grow = growbase + gr + 8;
                float2 nv = *(const float2*)(nid + (size_t)n*64 + c0);
                float m0 = ftanh(nacc[nt][2] + bb.x) + nv.x;
                float m1 = ftanh(nacc[nt][3] + bb.y) + nv.y;
                msgout[grow*32 + (c0 >> 1)] = make_float2(m0, m1);
                if (roflag && gr >= 4)
                    *(float2*)(s_ro + (gr-4)*64 + c0) = make_float2(m0, m1);
            }
        }
        __syncwarp();
        if (roflag) {
            size_t obase = ((size_t)b*TT + t)*2048 + (ntblk >> 1)*64;
            float v0 = 0.25f*(s_ro[ln]      + s_ro[64+ln]  + s_ro[128+ln] + s_ro[192+ln]);
            float v1 = 0.25f*(s_ro[32+ln]   + s_ro[96+ln]  + s_ro[160+ln] + s_ro[224+ln]);
            out[obase + ln]      = v0;
            out[obase + 32 + ln] = v1;
        }
    }
}

// ================= launcher =================
extern "C" void kernel_launch(void* const* d_in, const int* in_sizes, int n_in,
                              void* d_out, int out_size)
{
    const float* cc      = (const float*)d_in[0];
    const float* h_in    = (const float*)d_in[1];
    const float* msg_in  = (const float*)d_in[2];
    const float* wconn   = (const float*)d_in[3];
    const float* declog  = (const float*)d_in[4];
    const float* prim_in = (const float*)d_in[5];
    const float* heb     = (const float*)d_in[6];
    const float* sw1     = (const float*)d_in[7];
    const float* sb1     = (const float*)d_in[8];
    const float* sw2     = (const float*)d_in[9];
    const float* sb2     = (const float*)d_in[10];
    const float* mw1     = (const float*)d_in[11];
    const float* mb1     = (const float*)d_in[12];
    const float* mw2     = (const float*)d_in[13];
    const float* mb2     = (const float*)d_in[14];
    const float* modw1   = (const float*)d_in[15];
    const float* modb1   = (const float*)d_in[16];
    const float* modw2   = (const float*)d_in[17];
    const float* modb2   = (const float*)d_in[18];
    const float* nid     = (const float*)d_in[19];
    const int*   conn    = (const int*)d_in[20];
    float* out = (float*)d_out;

    cudaFuncSetAttribute(k_step, cudaFuncAttributeMaxDynamicSharedMemorySize, STEP_SMEM);

    k_init<<<256, 256>>>(h_in, msg_in, sw1, sw2, mw1, mw2);
    k_mod<<<NN, 256>>>(h_in, heb, declog, prim_in, wconn,
                       modw1, modb1, modw2, modb2, nid);
    k_const<<<dim3(512, 2), 256>>>(sb1, mb1, nid);

    for (int t = 0; t < TT; ++t) {
        k_step<<<dim3(NN/64, BSZ), 128, STEP_SMEM>>>(t, cc, conn, nid, sb2, mb2, out);
    }
}